// round 16
// baseline (speedup 1.0000x reference)
#include <cuda_runtime.h>
#include <cuda_fp16.h>
#include <cstdint>

#define NN   50000
#define IND  256
#define HID  128
#define OUTD 64
#define EMAX 800000

// scan config
#define SC_T     256
#define SC_I     2
#define SC_CHUNK (SC_T * SC_I)
#define SC_NB    ((NN + SC_CHUNK - 1) / SC_CHUNK)

// -------- device scratch --------
__device__ __half g_h1[NN * HID];    // RAW x@W1, fp16
__device__ __half g_agg1[NN * HID];  // layer-1 aggregation, fp16
__device__ __half g_h2[NN * OUTD];   // dinv-scaled relu(agg1+b1)@W2, fp16
__device__ float  g_dinv[NN];
__device__ int    g_deg[NN];
__device__ int    g_rowptr[NN + 1];
__device__ int    g_fill[NN];
__device__ int    g_csrc[EMAX];
__device__ int    g_bsum[SC_NB];
__device__ int    g_boff[SC_NB];
__device__ __half g_w1t[HID * IND];  // W1^T fp16
__device__ __half g_w2t[OUTD * HID]; // W2^T fp16

// ---------------- prep: deg=0 + both weight transposes (fp16) ----------------
__global__ void prep_kernel(int* __restrict__ deg,
                            const float* __restrict__ W1, const float* __restrict__ W2,
                            __half* __restrict__ T1, __half* __restrict__ T2) {
    int i = blockIdx.x * blockDim.x + threadIdx.x;
    if (i < NN) deg[i] = 0;
    const int n1 = IND * HID;
    const int n2 = HID * OUTD;
    if (i < n1) {
        int k = i / HID, n = i % HID;
        T1[(size_t)n * IND + k] = __float2half(W1[i]);
    } else if (i < n1 + n2) {
        int j = i - n1;
        int k = j / OUTD, n = j % OUTD;
        T2[(size_t)n * HID + k] = __float2half(W2[j]);
    }
}

__global__ void deg_count_kernel(const int* __restrict__ dst, int* __restrict__ deg, int E) {
    int i = blockIdx.x * blockDim.x + threadIdx.x;
    if (i < E) atomicAdd(&deg[dst[i]], 1);
}

// ---------------- scan chain ----------------
__global__ void scan_reduce_kernel(const int* __restrict__ deg, int* __restrict__ bsum,
                                   float* __restrict__ dinv, int n) {
    __shared__ int ws[SC_T / 32];
    int b = blockIdx.x, tid = threadIdx.x;
    int base = b * SC_CHUNK;
    int s = 0;
#pragma unroll
    for (int u = 0; u < SC_I; u++) {
        int i = base + u * SC_T + tid;
        if (i < n) {
            int c = deg[i];
            s += c;
            dinv[i] = rsqrtf((float)(c + 1));
        }
    }
#pragma unroll
    for (int d = 16; d; d >>= 1) s += __shfl_down_sync(0xffffffffu, s, d);
    if ((tid & 31) == 0) ws[tid >> 5] = s;
    __syncthreads();
    if (tid < 32) {
        int v = (tid < SC_T / 32) ? ws[tid] : 0;
#pragma unroll
        for (int d = 16; d; d >>= 1) v += __shfl_down_sync(0xffffffffu, v, d);
        if (tid == 0) bsum[b] = v;
    }
}

__global__ void scan_offsets_kernel(const int* __restrict__ bsum, int* __restrict__ boff,
                                    int* __restrict__ rowptr, int n) {
    __shared__ int ws[4];
    int tid = threadIdx.x;
    int lane = tid & 31, wid = tid >> 5;
    int v = (tid < SC_NB) ? bsum[tid] : 0;
    int x = v;
#pragma unroll
    for (int d = 1; d < 32; d <<= 1) {
        int y = __shfl_up_sync(0xffffffffu, x, d);
        if (lane >= d) x += y;
    }
    if (lane == 31) ws[wid] = x;
    __syncthreads();
    if (tid == 0) {
        int acc = 0;
#pragma unroll
        for (int k = 0; k < 4; k++) { int t = ws[k]; ws[k] = acc; acc += t; }
        rowptr[n] = acc;
    }
    __syncthreads();
    if (tid < SC_NB) boff[tid] = x - v + ws[wid];
}

__global__ void scan_write_kernel(const int* __restrict__ deg, const int* __restrict__ boff,
                                  int* __restrict__ rowptr, int* __restrict__ fill, int n) {
    __shared__ int sbuf[SC_CHUNK];
    __shared__ int ws[SC_T / 32];
    int b = blockIdx.x, tid = threadIdx.x;
    int lane = tid & 31, wid = tid >> 5;
    int base = b * SC_CHUNK;

#pragma unroll
    for (int u = 0; u < SC_I; u++) {
        int i = base + u * SC_T + tid;
        sbuf[u * SC_T + tid] = (i < n) ? deg[i] : 0;
    }
    __syncthreads();

    int v[SC_I];
    int tot = 0;
#pragma unroll
    for (int u = 0; u < SC_I; u++) {
        int d = sbuf[tid * SC_I + u];
        v[u] = tot;
        tot += d;
    }
    int x = tot;
#pragma unroll
    for (int d = 1; d < 32; d <<= 1) {
        int y = __shfl_up_sync(0xffffffffu, x, d);
        if (lane >= d) x += y;
    }
    if (lane == 31) ws[wid] = x;
    __syncthreads();
    if (wid == 0) {
        int y = (lane < SC_T / 32) ? ws[lane] : 0;
#pragma unroll
        for (int d = 1; d < 32; d <<= 1) {
            int z = __shfl_up_sync(0xffffffffu, y, d);
            if (lane >= d) y += z;
        }
        if (lane < SC_T / 32) ws[lane] = y;
    }
    __syncthreads();
    int off = boff[b] + (x - tot) + (wid ? ws[wid - 1] : 0);
#pragma unroll
    for (int u = 0; u < SC_I; u++) sbuf[tid * SC_I + u] = off + v[u];
    __syncthreads();

#pragma unroll
    for (int u = 0; u < SC_I; u++) {
        int i = base + u * SC_T + tid;
        if (i < n) {
            int r = sbuf[u * SC_T + tid];
            rowptr[i] = r;
            fill[i] = r;
        }
    }
}

__global__ void fill_kernel(const int* __restrict__ src, const int* __restrict__ dst,
                            int* __restrict__ fill, int* __restrict__ csrc, int E) {
    int i = blockIdx.x * blockDim.x + threadIdx.x;
    if (i >= E) return;
    int pos = atomicAdd(&fill[dst[i]], 1);
    csrc[pos] = src[i];
}

// ---------------- fp16 tensor-core GEMM with ldmatrix ----------------
#define MMA_F16(c, a, b) asm volatile( \
    "mma.sync.aligned.m16n8k16.row.col.f32.f16.f16.f32 " \
    "{%0,%1,%2,%3}, {%4,%5,%6,%7}, {%8,%9}, {%0,%1,%2,%3};" \
    : "+f"((c)[0]), "+f"((c)[1]), "+f"((c)[2]), "+f"((c)[3]) \
    : "r"((a)[0]), "r"((a)[1]), "r"((a)[2]), "r"((a)[3]), "r"((b)[0]), "r"((b)[1]))

__device__ __forceinline__ void ldsm_x4(uint32_t* r, uint32_t addr) {
    asm volatile("ldmatrix.sync.aligned.m8n8.x4.shared.b16 {%0,%1,%2,%3}, [%4];"
                 : "=r"(r[0]), "=r"(r[1]), "=r"(r[2]), "=r"(r[3]) : "r"(addr));
}

// HIN: A is __half (else float). FUSE: relu(A+bias[k]). SCALE: row scale. HOUT: half output.
template<int BN, int WGM, int WGN, bool HIN, bool FUSE, bool SCALE, bool HOUT>
__global__ __launch_bounds__(256, 2)
void mma_gemm_kernel(const void* __restrict__ Ain,
                     const __half* __restrict__ BT,
                     const float* __restrict__ bias,
                     const float* __restrict__ rowscale,
                     void* __restrict__ Cout, int M, int K) {
    constexpr int BM = 128, BK = 16, BKP = 24;
    constexpr int MI = BM / (WGM * 16);
    constexpr int NI = BN / (WGN * 8);
    constexpr int NBU2 = BN * 4 / 256;

    __shared__ __align__(16) __half sA[2][BM][BKP];
    __shared__ __align__(16) __half sB[2][BN][BKP];

    const int tid  = threadIdx.x;
    const int m0   = blockIdx.x * BM;
    const int w    = tid >> 5, lane = tid & 31;
    const int wm   = (w / WGN) * MI * 16;
    const int wn   = (w % WGN) * NI * 8;
    const int gid  = lane >> 2, tig = lane & 3;

    const int aRow  = lane & 15;
    const int aColB = (lane >> 4) * 16;
    const int bRow  = (lane & 7) + ((lane >> 4) << 3);
    const int bColB = ((lane >> 3) & 1) * 16;

    const uint32_t uA = (uint32_t)__cvta_generic_to_shared(&sA[0][0][0]);
    const uint32_t uB = (uint32_t)__cvta_generic_to_shared(&sB[0][0][0]);
    constexpr int ASTG = BM * BKP * 2;
    constexpr int BSTG = BN * BKP * 2;

    uint2 rA[2];     // staged A as packed half2 pairs
    uint2 rB[NBU2];

    float acc[MI][NI][4];
#pragma unroll
    for (int i = 0; i < MI; i++)
#pragma unroll
        for (int j = 0; j < NI; j++) {
            acc[i][j][0] = 0.f; acc[i][j][1] = 0.f; acc[i][j][2] = 0.f; acc[i][j][3] = 0.f;
        }

    auto loadA = [&](int k0) {
#pragma unroll
        for (int u = 0; u < 2; u++) {
            int idx = tid + u * 256;
            int row = idx >> 2;
            int c4  = idx & 3;
            int gm = m0 + row;
            int kk = k0 + c4 * 4;
            uint2 pk = make_uint2(0u, 0u);
            if (gm < M) {
                float4 v;
                if (HIN) {
                    const __half* Ah = (const __half*)Ain;
                    uint2 hv = *(const uint2*)(Ah + (size_t)gm * K + kk);
                    if (!FUSE) { rA[u] = hv; continue; }
                    float2 f0 = __half22float2(*(__half2*)&hv.x);
                    float2 f1 = __half22float2(*(__half2*)&hv.y);
                    v = make_float4(f0.x, f0.y, f1.x, f1.y);
                } else {
                    const float* Af = (const float*)Ain;
                    v = *(const float4*)(Af + (size_t)gm * K + kk);
                }
                if (FUSE) {
                    v.x = fmaxf(v.x + bias[kk + 0], 0.f);
                    v.y = fmaxf(v.y + bias[kk + 1], 0.f);
                    v.z = fmaxf(v.z + bias[kk + 2], 0.f);
                    v.w = fmaxf(v.w + bias[kk + 3], 0.f);
                }
                __half2 h0 = __floats2half2_rn(v.x, v.y);
                __half2 h1 = __floats2half2_rn(v.z, v.w);
                pk = make_uint2(*(uint32_t*)&h0, *(uint32_t*)&h1);
            }
            rA[u] = pk;
        }
    };
    auto loadB = [&](int k0) {
#pragma unroll
        for (int u = 0; u < NBU2; u++) {
            int idx = tid + u * 256;
            int n = idx >> 2;
            int c = idx & 3;
            rB[u] = *(const uint2*)(BT + (size_t)n * K + k0 + c * 4);
        }
    };
    auto storeTile = [&](int buf) {
#pragma unroll
        for (int u = 0; u < 2; u++) {
            int idx = tid + u * 256;
            int row = idx >> 2;
            int c4  = idx & 3;
            *(uint2*)&sA[buf][row][c4 * 4] = rA[u];
        }
#pragma unroll
        for (int u = 0; u < NBU2; u++) {
            int idx = tid + u * 256;
            int n = idx >> 2;
            int c = idx & 3;
            *(uint2*)&sB[buf][n][c * 4] = rB[u];
        }
    };

    const int nIter = K / BK;
    loadA(0); loadB(0);
    storeTile(0);
    __syncthreads();

    for (int it = 0; it < nIter; ++it) {
        if (it + 1 < nIter) { loadA((it + 1) * BK); loadB((it + 1) * BK); }
        const int p = it & 1;

        uint32_t af[MI][4];
        {
            uint32_t aBase = p * ASTG + (wm + aRow) * (BKP * 2) + aColB;
#pragma unroll
            for (int mi = 0; mi < MI; mi++)
                ldsm_x4(af[mi], uA + aBase + mi * 16 * (BKP * 2));
        }
        uint32_t bf[NI][2];
        {
            uint32_t bBase = p * BSTG + (wn + bRow) * (BKP * 2) + bColB;
#pragma unroll
            for (int q = 0; q < NI / 2; q++)
                ldsm_x4(&bf[2 * q][0], uB + bBase + q * 16 * (BKP * 2));
        }
#pragma unroll
        for (int mi = 0; mi < MI; mi++)
#pragma unroll
            for (int ni = 0; ni < NI; ni++)
                MMA_F16(acc[mi][ni], af[mi], bf[ni]);

        if (it + 1 < nIter) storeTile((it + 1) & 1);
        __syncthreads();
    }

#pragma unroll
    for (int mi = 0; mi < MI; mi++) {
        int r0 = m0 + wm + mi * 16 + gid;
        int r1 = r0 + 8;
        float s0 = 1.f, s1 = 1.f;
        if (SCALE) {
            s0 = (r0 < M) ? rowscale[r0] : 0.f;
            s1 = (r1 < M) ? rowscale[r1] : 0.f;
        }
#pragma unroll
        for (int ni = 0; ni < NI; ni++) {
            int col = wn + ni * 8 + 2 * tig;
            if (HOUT) {
                __half* C = (__half*)Cout;
                if (r0 < M)
                    *(__half2*)(C + (size_t)r0 * BN + col) =
                        __floats2half2_rn(acc[mi][ni][0] * s0, acc[mi][ni][1] * s0);
                if (r1 < M)
                    *(__half2*)(C + (size_t)r1 * BN + col) =
                        __floats2half2_rn(acc[mi][ni][2] * s1, acc[mi][ni][3] * s1);
            } else {
                float* C = (float*)Cout;
                if (r0 < M)
                    *(float2*)(C + (size_t)r0 * BN + col) =
                        make_float2(acc[mi][ni][0] * s0, acc[mi][ni][1] * s0);
                if (r1 < M)
                    *(float2*)(C + (size_t)r1 * BN + col) =
                        make_float2(acc[mi][ni][2] * s1, acc[mi][ni][3] * s1);
            }
        }
    }
}

// ---------------- CSR gather aggregation ----------------
// h1 RAW fp16 (row = 32 uint2); out fp16:
// agg[d] = dinv[d] * ( sum_s dinv[s]*h1[s] + dinv[d]*h1[d] )
__global__ void gather128_kernel(const uint2* __restrict__ hs, const int* __restrict__ csrc,
                                 const int* __restrict__ rowptr, const float* __restrict__ dinv,
                                 uint2* __restrict__ out) {
    int w = (blockIdx.x * blockDim.x + threadIdx.x) >> 5;
    if (w >= NN) return;
    int lane = threadIdx.x & 31;
    int begin = rowptr[w], end = rowptr[w + 1];
    float dv = __ldg(&dinv[w]);
    uint2 sv = __ldg(&hs[(size_t)w * 32 + lane]);
    float2 sf0 = __half22float2(*(__half2*)&sv.x);
    float2 sf1 = __half22float2(*(__half2*)&sv.y);
    float4 a[8];
    a[0].x = dv * sf0.x; a[0].y = dv * sf0.y; a[0].z = dv * sf1.x; a[0].w = dv * sf1.y;
#pragma unroll
    for (int q = 1; q < 8; q++) a[q] = make_float4(0.f, 0.f, 0.f, 0.f);
    int j = begin;
    for (; j + 8 <= end; j += 8) {
        int   si[8];
        float wi[8];
        uint2 vi[8];
#pragma unroll
        for (int q = 0; q < 8; q++) si[q] = __ldg(&csrc[j + q]);
#pragma unroll
        for (int q = 0; q < 8; q++) wi[q] = __ldg(&dinv[si[q]]);
#pragma unroll
        for (int q = 0; q < 8; q++) vi[q] = __ldg(&hs[(size_t)si[q] * 32 + lane]);
#pragma unroll
        for (int q = 0; q < 8; q++) {
            float2 f0 = __half22float2(*(__half2*)&vi[q].x);
            float2 f1 = __half22float2(*(__half2*)&vi[q].y);
            a[q].x = fmaf(wi[q], f0.x, a[q].x);
            a[q].y = fmaf(wi[q], f0.y, a[q].y);
            a[q].z = fmaf(wi[q], f1.x, a[q].z);
            a[q].w = fmaf(wi[q], f1.y, a[q].w);
        }
    }
    for (; j < end; ++j) {
        int s0 = __ldg(&csrc[j]);
        float w0 = __ldg(&dinv[s0]);
        uint2 v0 = __ldg(&hs[(size_t)s0 * 32 + lane]);
        float2 f0 = __half22float2(*(__half2*)&v0.x);
        float2 f1 = __half22float2(*(__half2*)&v0.y);
        a[0].x = fmaf(w0, f0.x, a[0].x); a[0].y = fmaf(w0, f0.y, a[0].y);
        a[0].z = fmaf(w0, f1.x, a[0].z); a[0].w = fmaf(w0, f1.y, a[0].w);
    }
#pragma unroll
    for (int q = 1; q < 8; q++) {
        a[0].x += a[q].x; a[0].y += a[q].y; a[0].z += a[q].z; a[0].w += a[q].w;
    }
    __half2 r0 = __floats2half2_rn(dv * a[0].x, dv * a[0].y);
    __half2 r1 = __floats2half2_rn(dv * a[0].z, dv * a[0].w);
    out[(size_t)w * 32 + lane] = make_uint2(*(uint32_t*)&r0, *(uint32_t*)&r1);
}

// h2 fp16 pre-scaled (row = 32 half2): out[d] = dinv[d]*(sum + h2[d]) + b2  (fp32 out)
__global__ void gather64_kernel(const uint32_t* __restrict__ hs, const int* __restrict__ csrc,
                                const int* __restrict__ rowptr, const float* __restrict__ dinv,
                                const float* __restrict__ b2, float2* __restrict__ out) {
    int w = (blockIdx.x * blockDim.x + threadIdx.x) >> 5;
    if (w >= NN) return;
    int lane = threadIdx.x & 31;
    int begin = rowptr[w], end = rowptr[w + 1];
    uint32_t sv = __ldg(&hs[(size_t)w * 32 + lane]);
    float2 a0 = __half22float2(*(__half2*)&sv);
    float2 a1 = make_float2(0.f, 0.f);
    float2 a2 = make_float2(0.f, 0.f);
    float2 a3 = make_float2(0.f, 0.f);
    int j = begin;
    for (; j + 4 <= end; j += 4) {
        int s0 = __ldg(&csrc[j]);
        int s1 = __ldg(&csrc[j + 1]);
        int s2 = __ldg(&csrc[j + 2]);
        int s3 = __ldg(&csrc[j + 3]);
        uint32_t v0 = __ldg(&hs[(size_t)s0 * 32 + lane]);
        uint32_t v1 = __ldg(&hs[(size_t)s1 * 32 + lane]);
        uint32_t v2 = __ldg(&hs[(size_t)s2 * 32 + lane]);
        uint32_t v3 = __ldg(&hs[(size_t)s3 * 32 + lane]);
        float2 f;
        f = __half22float2(*(__half2*)&v0); a0.x += f.x; a0.y += f.y;
        f = __half22float2(*(__half2*)&v1); a1.x += f.x; a1.y += f.y;
        f = __half22float2(*(__half2*)&v2); a2.x += f.x; a2.y += f.y;
        f = __half22float2(*(__half2*)&v3); a3.x += f.x; a3.y += f.y;
    }
    for (; j < end; ++j) {
        int s0 = __ldg(&csrc[j]);
        uint32_t v0 = __ldg(&hs[(size_t)s0 * 32 + lane]);
        float2 f = __half22float2(*(__half2*)&v0);
        a0.x += f.x; a0.y += f.y;
    }
    float dv = dinv[w];
    float2 r;
    r.x = dv * ((a0.x + a1.x) + (a2.x + a3.x)) + b2[lane * 2 + 0];
    r.y = dv * ((a0.y + a1.y) + (a2.y + a3.y)) + b2[lane * 2 + 1];
    out[(size_t)w * 32 + lane] = r;
}

// ---------------- launch ----------------
extern "C" void kernel_launch(void* const* d_in, const int* in_sizes, int n_in,
                              void* d_out, int out_size) {
    const float* x   = (const float*)d_in[0];
    const int*   ei  = (const int*)d_in[1];   // int32 (JAX x64 disabled)
    const float* W1  = (const float*)d_in[2];
    const float* b1  = (const float*)d_in[3];
    const float* W2  = (const float*)d_in[4];
    const float* b2  = (const float*)d_in[5];
    float*       out = (float*)d_out;

    const int E = in_sizes[1] / 2;
    const int* src = ei;
    const int* dst = ei + E;

    void* p;
    cudaGetSymbolAddress(&p, g_h1);     __half* h1    = (__half*)p;
    cudaGetSymbolAddress(&p, g_agg1);   __half* agg1  = (__half*)p;
    cudaGetSymbolAddress(&p, g_h2);     __half* h2    = (__half*)p;
    cudaGetSymbolAddress(&p, g_dinv);   float* dinv   = (float*)p;
    cudaGetSymbolAddress(&p, g_deg);    int*   deg    = (int*)p;
    cudaGetSymbolAddress(&p, g_rowptr); int*   rowptr = (int*)p;
    cudaGetSymbolAddress(&p, g_fill);   int*   fill   = (int*)p;
    cudaGetSymbolAddress(&p, g_csrc);   int*   csrc   = (int*)p;
    cudaGetSymbolAddress(&p, g_bsum);   int*   bsum   = (int*)p;
    cudaGetSymbolAddress(&p, g_boff);   int*   boff   = (int*)p;
    cudaGetSymbolAddress(&p, g_w1t);    __half* w1t   = (__half*)p;
    cudaGetSymbolAddress(&p, g_w2t);    __half* w2t   = (__half*)p;

    static cudaStream_t s1 = nullptr;
    static cudaEvent_t  ePrep = nullptr, eGemm1 = nullptr;
    if (!s1) {
        cudaStreamCreateWithFlags(&s1, cudaStreamNonBlocking);
        cudaEventCreateWithFlags(&ePrep,  cudaEventDisableTiming);
        cudaEventCreateWithFlags(&eGemm1, cudaEventDisableTiming);
    }

    const int warpsGrid = (NN * 32 + 255) / 256;
    const int gemmGrid  = (NN + 127) / 128;

    // ---- main: prep (deg=0 + weight transposes) ----
    prep_kernel<<<(NN + 255) / 256, 256>>>(deg, W1, W2, w1t, w2t);
    cudaEventRecord(ePrep, 0);

    // ---- s1: GEMM1 (fp32 in, raw fp16 out) starts right after prep ----
    cudaStreamWaitEvent(s1, ePrep, 0);
    mma_gemm_kernel<HID, 2, 4, false, false, false, true><<<gemmGrid, 256, 0, s1>>>(
        x, w1t, nullptr, nullptr, h1, NN, IND);
    cudaEventRecord(eGemm1, s1);

    // ---- main: CSR chain overlaps GEMM1 ----
    deg_count_kernel<<<(E + 255) / 256, 256>>>(dst, deg, E);
    scan_reduce_kernel<<<SC_NB, SC_T>>>(deg, bsum, dinv, NN);
    scan_offsets_kernel<<<1, 128>>>(bsum, boff, rowptr, NN);
    scan_write_kernel<<<SC_NB, SC_T>>>(deg, boff, rowptr, fill, NN);
    fill_kernel<<<(E + 255) / 256, 256>>>(src, dst, fill, csrc, E);

    // ---- join, serial tail ----
    cudaStreamWaitEvent(0, eGemm1, 0);
    gather128_kernel<<<warpsGrid, 256>>>((const uint2*)h1, csrc, rowptr, dinv, (uint2*)agg1);
    mma_gemm_kernel<OUTD, 4, 2, true, true, true, true><<<gemmGrid, 256>>>(
        agg1, w2t, b1, dinv, h2, NN, HID);
    gather64_kernel<<<warpsGrid, 256>>>((const uint32_t*)h2, csrc, rowptr, dinv, b2, (float2*)out);
}

// round 17
// speedup vs baseline: 1.0667x; 1.0667x over previous
#include <cuda_runtime.h>
#include <cuda_fp16.h>
#include <cstdint>

#define NN   50000
#define IND  256
#define HID  128
#define OUTD 64
#define EMAX 800000

// scan config
#define SC_T     256
#define SC_I     2
#define SC_CHUNK (SC_T * SC_I)
#define SC_NB    ((NN + SC_CHUNK - 1) / SC_CHUNK)

// -------- device scratch --------
__device__ __half g_h1[NN * HID];    // RAW x@W1, fp16
__device__ __half g_agg1[NN * HID];  // layer-1 aggregation, fp16
__device__ __half g_h2[NN * OUTD];   // dinv-scaled relu(agg1+b1)@W2, fp16
__device__ float  g_dinv[NN];
__device__ int    g_deg[NN];
__device__ int    g_rowptr[NN + 1];
__device__ int    g_fill[NN];
__device__ int    g_csrc[EMAX];
__device__ int    g_bsum[SC_NB];
__device__ int    g_boff[SC_NB];
__device__ __half g_w1t[HID * IND];  // W1^T fp16
__device__ __half g_w2t[OUTD * HID]; // W2^T fp16

// ---------------- prep: deg=0 + both weight transposes (fp16) ----------------
__global__ void prep_kernel(int* __restrict__ deg,
                            const float* __restrict__ W1, const float* __restrict__ W2,
                            __half* __restrict__ T1, __half* __restrict__ T2) {
    int i = blockIdx.x * blockDim.x + threadIdx.x;
    if (i < NN) deg[i] = 0;
    const int n1 = IND * HID;
    const int n2 = HID * OUTD;
    if (i < n1) {
        int k = i / HID, n = i % HID;
        T1[(size_t)n * IND + k] = __float2half(W1[i]);
    } else if (i < n1 + n2) {
        int j = i - n1;
        int k = j / OUTD, n = j % OUTD;
        T2[(size_t)n * HID + k] = __float2half(W2[j]);
    }
}

__global__ void deg_count_kernel(const int* __restrict__ dst, int* __restrict__ deg, int E) {
    int i = blockIdx.x * blockDim.x + threadIdx.x;
    if (i < E) atomicAdd(&deg[dst[i]], 1);
}

// ---------------- scan chain ----------------
__global__ void scan_reduce_kernel(const int* __restrict__ deg, int* __restrict__ bsum,
                                   float* __restrict__ dinv, int n) {
    __shared__ int ws[SC_T / 32];
    int b = blockIdx.x, tid = threadIdx.x;
    int base = b * SC_CHUNK;
    int s = 0;
#pragma unroll
    for (int u = 0; u < SC_I; u++) {
        int i = base + u * SC_T + tid;
        if (i < n) {
            int c = deg[i];
            s += c;
            dinv[i] = rsqrtf((float)(c + 1));
        }
    }
#pragma unroll
    for (int d = 16; d; d >>= 1) s += __shfl_down_sync(0xffffffffu, s, d);
    if ((tid & 31) == 0) ws[tid >> 5] = s;
    __syncthreads();
    if (tid < 32) {
        int v = (tid < SC_T / 32) ? ws[tid] : 0;
#pragma unroll
        for (int d = 16; d; d >>= 1) v += __shfl_down_sync(0xffffffffu, v, d);
        if (tid == 0) bsum[b] = v;
    }
}

__global__ void scan_offsets_kernel(const int* __restrict__ bsum, int* __restrict__ boff,
                                    int* __restrict__ rowptr, int n) {
    __shared__ int ws[4];
    int tid = threadIdx.x;
    int lane = tid & 31, wid = tid >> 5;
    int v = (tid < SC_NB) ? bsum[tid] : 0;
    int x = v;
#pragma unroll
    for (int d = 1; d < 32; d <<= 1) {
        int y = __shfl_up_sync(0xffffffffu, x, d);
        if (lane >= d) x += y;
    }
    if (lane == 31) ws[wid] = x;
    __syncthreads();
    if (tid == 0) {
        int acc = 0;
#pragma unroll
        for (int k = 0; k < 4; k++) { int t = ws[k]; ws[k] = acc; acc += t; }
        rowptr[n] = acc;
    }
    __syncthreads();
    if (tid < SC_NB) boff[tid] = x - v + ws[wid];
}

__global__ void scan_write_kernel(const int* __restrict__ deg, const int* __restrict__ boff,
                                  int* __restrict__ rowptr, int* __restrict__ fill, int n) {
    __shared__ int sbuf[SC_CHUNK];
    __shared__ int ws[SC_T / 32];
    int b = blockIdx.x, tid = threadIdx.x;
    int lane = tid & 31, wid = tid >> 5;
    int base = b * SC_CHUNK;

#pragma unroll
    for (int u = 0; u < SC_I; u++) {
        int i = base + u * SC_T + tid;
        sbuf[u * SC_T + tid] = (i < n) ? deg[i] : 0;
    }
    __syncthreads();

    int v[SC_I];
    int tot = 0;
#pragma unroll
    for (int u = 0; u < SC_I; u++) {
        int d = sbuf[tid * SC_I + u];
        v[u] = tot;
        tot += d;
    }
    int x = tot;
#pragma unroll
    for (int d = 1; d < 32; d <<= 1) {
        int y = __shfl_up_sync(0xffffffffu, x, d);
        if (lane >= d) x += y;
    }
    if (lane == 31) ws[wid] = x;
    __syncthreads();
    if (wid == 0) {
        int y = (lane < SC_T / 32) ? ws[lane] : 0;
#pragma unroll
        for (int d = 1; d < 32; d <<= 1) {
            int z = __shfl_up_sync(0xffffffffu, y, d);
            if (lane >= d) y += z;
        }
        if (lane < SC_T / 32) ws[lane] = y;
    }
    __syncthreads();
    int off = boff[b] + (x - tot) + (wid ? ws[wid - 1] : 0);
#pragma unroll
    for (int u = 0; u < SC_I; u++) sbuf[tid * SC_I + u] = off + v[u];
    __syncthreads();

#pragma unroll
    for (int u = 0; u < SC_I; u++) {
        int i = base + u * SC_T + tid;
        if (i < n) {
            int r = sbuf[u * SC_T + tid];
            rowptr[i] = r;
            fill[i] = r;
        }
    }
}

__global__ void fill_kernel(const int* __restrict__ src, const int* __restrict__ dst,
                            int* __restrict__ fill, int* __restrict__ csrc, int E) {
    int i = blockIdx.x * blockDim.x + threadIdx.x;
    if (i >= E) return;
    int pos = atomicAdd(&fill[dst[i]], 1);
    csrc[pos] = src[i];
}

// ---------------- fp16 tensor-core GEMM with ldmatrix ----------------
#define MMA_F16(c, a, b) asm volatile( \
    "mma.sync.aligned.m16n8k16.row.col.f32.f16.f16.f32 " \
    "{%0,%1,%2,%3}, {%4,%5,%6,%7}, {%8,%9}, {%0,%1,%2,%3};" \
    : "+f"((c)[0]), "+f"((c)[1]), "+f"((c)[2]), "+f"((c)[3]) \
    : "r"((a)[0]), "r"((a)[1]), "r"((a)[2]), "r"((a)[3]), "r"((b)[0]), "r"((b)[1]))

__device__ __forceinline__ void ldsm_x4(uint32_t* r, uint32_t addr) {
    asm volatile("ldmatrix.sync.aligned.m8n8.x4.shared.b16 {%0,%1,%2,%3}, [%4];"
                 : "=r"(r[0]), "=r"(r[1]), "=r"(r[2]), "=r"(r[3]) : "r"(addr));
}

// HIN: A is __half (else float). FUSE: relu(A+bias[k]). SCALE: row scale. HOUT: half output.
template<int BN, int WGM, int WGN, bool HIN, bool FUSE, bool SCALE, bool HOUT>
__global__ __launch_bounds__(256, 2)
void mma_gemm_kernel(const void* __restrict__ Ain,
                     const __half* __restrict__ BT,
                     const float* __restrict__ bias,
                     const float* __restrict__ rowscale,
                     void* __restrict__ Cout, int M, int K) {
    constexpr int BM = 128, BK = 16, BKP = 24;
    constexpr int MI = BM / (WGM * 16);
    constexpr int NI = BN / (WGN * 8);
    constexpr int NBU2 = BN * 4 / 256;

    __shared__ __align__(16) __half sA[2][BM][BKP];
    __shared__ __align__(16) __half sB[2][BN][BKP];

    const int tid  = threadIdx.x;
    const int m0   = blockIdx.x * BM;
    const int w    = tid >> 5, lane = tid & 31;
    const int wm   = (w / WGN) * MI * 16;
    const int wn   = (w % WGN) * NI * 8;
    const int gid  = lane >> 2, tig = lane & 3;

    const int aRow  = lane & 15;
    const int aColB = (lane >> 4) * 16;
    const int bRow  = (lane & 7) + ((lane >> 4) << 3);
    const int bColB = ((lane >> 3) & 1) * 16;

    const uint32_t uA = (uint32_t)__cvta_generic_to_shared(&sA[0][0][0]);
    const uint32_t uB = (uint32_t)__cvta_generic_to_shared(&sB[0][0][0]);
    constexpr int ASTG = BM * BKP * 2;
    constexpr int BSTG = BN * BKP * 2;

    uint2 rA[2];     // staged A as packed half2 pairs
    uint2 rB[NBU2];

    float acc[MI][NI][4];
#pragma unroll
    for (int i = 0; i < MI; i++)
#pragma unroll
        for (int j = 0; j < NI; j++) {
            acc[i][j][0] = 0.f; acc[i][j][1] = 0.f; acc[i][j][2] = 0.f; acc[i][j][3] = 0.f;
        }

    auto loadA = [&](int k0) {
#pragma unroll
        for (int u = 0; u < 2; u++) {
            int idx = tid + u * 256;
            int row = idx >> 2;
            int c4  = idx & 3;
            int gm = m0 + row;
            int kk = k0 + c4 * 4;
            uint2 pk = make_uint2(0u, 0u);
            if (gm < M) {
                float4 v;
                if (HIN) {
                    const __half* Ah = (const __half*)Ain;
                    uint2 hv = *(const uint2*)(Ah + (size_t)gm * K + kk);
                    if (!FUSE) { rA[u] = hv; continue; }
                    float2 f0 = __half22float2(*(__half2*)&hv.x);
                    float2 f1 = __half22float2(*(__half2*)&hv.y);
                    v = make_float4(f0.x, f0.y, f1.x, f1.y);
                } else {
                    const float* Af = (const float*)Ain;
                    v = *(const float4*)(Af + (size_t)gm * K + kk);
                }
                if (FUSE) {
                    v.x = fmaxf(v.x + bias[kk + 0], 0.f);
                    v.y = fmaxf(v.y + bias[kk + 1], 0.f);
                    v.z = fmaxf(v.z + bias[kk + 2], 0.f);
                    v.w = fmaxf(v.w + bias[kk + 3], 0.f);
                }
                __half2 h0 = __floats2half2_rn(v.x, v.y);
                __half2 h1 = __floats2half2_rn(v.z, v.w);
                pk = make_uint2(*(uint32_t*)&h0, *(uint32_t*)&h1);
            }
            rA[u] = pk;
        }
    };
    auto loadB = [&](int k0) {
#pragma unroll
        for (int u = 0; u < NBU2; u++) {
            int idx = tid + u * 256;
            int n = idx >> 2;
            int c = idx & 3;
            rB[u] = *(const uint2*)(BT + (size_t)n * K + k0 + c * 4);
        }
    };
    auto storeTile = [&](int buf) {
#pragma unroll
        for (int u = 0; u < 2; u++) {
            int idx = tid + u * 256;
            int row = idx >> 2;
            int c4  = idx & 3;
            *(uint2*)&sA[buf][row][c4 * 4] = rA[u];
        }
#pragma unroll
        for (int u = 0; u < NBU2; u++) {
            int idx = tid + u * 256;
            int n = idx >> 2;
            int c = idx & 3;
            *(uint2*)&sB[buf][n][c * 4] = rB[u];
        }
    };

    const int nIter = K / BK;
    loadA(0); loadB(0);
    storeTile(0);
    __syncthreads();

    for (int it = 0; it < nIter; ++it) {
        if (it + 1 < nIter) { loadA((it + 1) * BK); loadB((it + 1) * BK); }
        const int p = it & 1;

        uint32_t af[MI][4];
        {
            uint32_t aBase = p * ASTG + (wm + aRow) * (BKP * 2) + aColB;
#pragma unroll
            for (int mi = 0; mi < MI; mi++)
                ldsm_x4(af[mi], uA + aBase + mi * 16 * (BKP * 2));
        }
        uint32_t bf[NI][2];
        {
            uint32_t bBase = p * BSTG + (wn + bRow) * (BKP * 2) + bColB;
#pragma unroll
            for (int q = 0; q < NI / 2; q++)
                ldsm_x4(&bf[2 * q][0], uB + bBase + q * 16 * (BKP * 2));
        }
#pragma unroll
        for (int mi = 0; mi < MI; mi++)
#pragma unroll
            for (int ni = 0; ni < NI; ni++)
                MMA_F16(acc[mi][ni], af[mi], bf[ni]);

        if (it + 1 < nIter) storeTile((it + 1) & 1);
        __syncthreads();
    }

#pragma unroll
    for (int mi = 0; mi < MI; mi++) {
        int r0 = m0 + wm + mi * 16 + gid;
        int r1 = r0 + 8;
        float s0 = 1.f, s1 = 1.f;
        if (SCALE) {
            s0 = (r0 < M) ? rowscale[r0] : 0.f;
            s1 = (r1 < M) ? rowscale[r1] : 0.f;
        }
#pragma unroll
        for (int ni = 0; ni < NI; ni++) {
            int col = wn + ni * 8 + 2 * tig;
            if (HOUT) {
                __half* C = (__half*)Cout;
                if (r0 < M)
                    *(__half2*)(C + (size_t)r0 * BN + col) =
                        __floats2half2_rn(acc[mi][ni][0] * s0, acc[mi][ni][1] * s0);
                if (r1 < M)
                    *(__half2*)(C + (size_t)r1 * BN + col) =
                        __floats2half2_rn(acc[mi][ni][2] * s1, acc[mi][ni][3] * s1);
            } else {
                float* C = (float*)Cout;
                if (r0 < M)
                    *(float2*)(C + (size_t)r0 * BN + col) =
                        make_float2(acc[mi][ni][0] * s0, acc[mi][ni][1] * s0);
                if (r1 < M)
                    *(float2*)(C + (size_t)r1 * BN + col) =
                        make_float2(acc[mi][ni][2] * s1, acc[mi][ni][3] * s1);
            }
        }
    }
}

// ---------------- CSR gather aggregation ----------------
// h1 RAW fp16 (row = 32 uint2); out fp16 (4-way unroll, R15 structure):
// agg[d] = dinv[d] * ( sum_s dinv[s]*h1[s] + dinv[d]*h1[d] )
__global__ void gather128_kernel(const uint2* __restrict__ hs, const int* __restrict__ csrc,
                                 const int* __restrict__ rowptr, const float* __restrict__ dinv,
                                 uint2* __restrict__ out) {
    int w = (blockIdx.x * blockDim.x + threadIdx.x) >> 5;
    if (w >= NN) return;
    int lane = threadIdx.x & 31;
    int begin = rowptr[w], end = rowptr[w + 1];
    float dv = __ldg(&dinv[w]);
    uint2 sv = __ldg(&hs[(size_t)w * 32 + lane]);
    float2 sf0 = __half22float2(*(__half2*)&sv.x);
    float2 sf1 = __half22float2(*(__half2*)&sv.y);
    float4 a0, a1, a2, a3;
    a0.x = dv * sf0.x; a0.y = dv * sf0.y; a0.z = dv * sf1.x; a0.w = dv * sf1.y;
    a1 = make_float4(0.f, 0.f, 0.f, 0.f);
    a2 = make_float4(0.f, 0.f, 0.f, 0.f);
    a3 = make_float4(0.f, 0.f, 0.f, 0.f);
    int j = begin;
    for (; j + 4 <= end; j += 4) {
        int s0 = __ldg(&csrc[j]);
        int s1 = __ldg(&csrc[j + 1]);
        int s2 = __ldg(&csrc[j + 2]);
        int s3 = __ldg(&csrc[j + 3]);
        float w0 = __ldg(&dinv[s0]);
        float w1 = __ldg(&dinv[s1]);
        float w2 = __ldg(&dinv[s2]);
        float w3 = __ldg(&dinv[s3]);
        uint2 v0 = __ldg(&hs[(size_t)s0 * 32 + lane]);
        uint2 v1 = __ldg(&hs[(size_t)s1 * 32 + lane]);
        uint2 v2 = __ldg(&hs[(size_t)s2 * 32 + lane]);
        uint2 v3 = __ldg(&hs[(size_t)s3 * 32 + lane]);
        float2 f;
        f = __half22float2(*(__half2*)&v0.x); a0.x = fmaf(w0, f.x, a0.x); a0.y = fmaf(w0, f.y, a0.y);
        f = __half22float2(*(__half2*)&v0.y); a0.z = fmaf(w0, f.x, a0.z); a0.w = fmaf(w0, f.y, a0.w);
        f = __half22float2(*(__half2*)&v1.x); a1.x = fmaf(w1, f.x, a1.x); a1.y = fmaf(w1, f.y, a1.y);
        f = __half22float2(*(__half2*)&v1.y); a1.z = fmaf(w1, f.x, a1.z); a1.w = fmaf(w1, f.y, a1.w);
        f = __half22float2(*(__half2*)&v2.x); a2.x = fmaf(w2, f.x, a2.x); a2.y = fmaf(w2, f.y, a2.y);
        f = __half22float2(*(__half2*)&v2.y); a2.z = fmaf(w2, f.x, a2.z); a2.w = fmaf(w2, f.y, a2.w);
        f = __half22float2(*(__half2*)&v3.x); a3.x = fmaf(w3, f.x, a3.x); a3.y = fmaf(w3, f.y, a3.y);
        f = __half22float2(*(__half2*)&v3.y); a3.z = fmaf(w3, f.x, a3.z); a3.w = fmaf(w3, f.y, a3.w);
    }
    for (; j < end; ++j) {
        int s0 = __ldg(&csrc[j]);
        float w0 = __ldg(&dinv[s0]);
        uint2 v0 = __ldg(&hs[(size_t)s0 * 32 + lane]);
        float2 f;
        f = __half22float2(*(__half2*)&v0.x); a0.x = fmaf(w0, f.x, a0.x); a0.y = fmaf(w0, f.y, a0.y);
        f = __half22float2(*(__half2*)&v0.y); a0.z = fmaf(w0, f.x, a0.z); a0.w = fmaf(w0, f.y, a0.w);
    }
    float rx = dv * ((a0.x + a1.x) + (a2.x + a3.x));
    float ry = dv * ((a0.y + a1.y) + (a2.y + a3.y));
    float rz = dv * ((a0.z + a1.z) + (a2.z + a3.z));
    float rw = dv * ((a0.w + a1.w) + (a2.w + a3.w));
    __half2 r0 = __floats2half2_rn(rx, ry);
    __half2 r1 = __floats2half2_rn(rz, rw);
    out[(size_t)w * 32 + lane] = make_uint2(*(uint32_t*)&r0, *(uint32_t*)&r1);
}

// h2 fp16 pre-scaled (row = 32 half2): out[d] = dinv[d]*(sum + h2[d]) + b2  (fp32 out)
__global__ void gather64_kernel(const uint32_t* __restrict__ hs, const int* __restrict__ csrc,
                                const int* __restrict__ rowptr, const float* __restrict__ dinv,
                                const float* __restrict__ b2, float2* __restrict__ out) {
    int w = (blockIdx.x * blockDim.x + threadIdx.x) >> 5;
    if (w >= NN) return;
    int lane = threadIdx.x & 31;
    int begin = rowptr[w], end = rowptr[w + 1];
    uint32_t sv = __ldg(&hs[(size_t)w * 32 + lane]);
    float2 a0 = __half22float2(*(__half2*)&sv);
    float2 a1 = make_float2(0.f, 0.f);
    float2 a2 = make_float2(0.f, 0.f);
    float2 a3 = make_float2(0.f, 0.f);
    int j = begin;
    for (; j + 4 <= end; j += 4) {
        int s0 = __ldg(&csrc[j]);
        int s1 = __ldg(&csrc[j + 1]);
        int s2 = __ldg(&csrc[j + 2]);
        int s3 = __ldg(&csrc[j + 3]);
        uint32_t v0 = __ldg(&hs[(size_t)s0 * 32 + lane]);
        uint32_t v1 = __ldg(&hs[(size_t)s1 * 32 + lane]);
        uint32_t v2 = __ldg(&hs[(size_t)s2 * 32 + lane]);
        uint32_t v3 = __ldg(&hs[(size_t)s3 * 32 + lane]);
        float2 f;
        f = __half22float2(*(__half2*)&v0); a0.x += f.x; a0.y += f.y;
        f = __half22float2(*(__half2*)&v1); a1.x += f.x; a1.y += f.y;
        f = __half22float2(*(__half2*)&v2); a2.x += f.x; a2.y += f.y;
        f = __half22float2(*(__half2*)&v3); a3.x += f.x; a3.y += f.y;
    }
    for (; j < end; ++j) {
        int s0 = __ldg(&csrc[j]);
        uint32_t v0 = __ldg(&hs[(size_t)s0 * 32 + lane]);
        float2 f = __half22float2(*(__half2*)&v0);
        a0.x += f.x; a0.y += f.y;
    }
    float dv = dinv[w];
    float2 r;
    r.x = dv * ((a0.x + a1.x) + (a2.x + a3.x)) + b2[lane * 2 + 0];
    r.y = dv * ((a0.y + a1.y) + (a2.y + a3.y)) + b2[lane * 2 + 1];
    out[(size_t)w * 32 + lane] = r;
}

// ---------------- launch ----------------
extern "C" void kernel_launch(void* const* d_in, const int* in_sizes, int n_in,
                              void* d_out, int out_size) {
    const float* x   = (const float*)d_in[0];
    const int*   ei  = (const int*)d_in[1];   // int32 (JAX x64 disabled)
    const float* W1  = (const float*)d_in[2];
    const float* b1  = (const float*)d_in[3];
    const float* W2  = (const float*)d_in[4];
    const float* b2  = (const float*)d_in[5];
    float*       out = (float*)d_out;

    const int E = in_sizes[1] / 2;
    const int* src = ei;
    const int* dst = ei + E;

    void* p;
    cudaGetSymbolAddress(&p, g_h1);     __half* h1    = (__half*)p;
    cudaGetSymbolAddress(&p, g_agg1);   __half* agg1  = (__half*)p;
    cudaGetSymbolAddress(&p, g_h2);     __half* h2    = (__half*)p;
    cudaGetSymbolAddress(&p, g_dinv);   float* dinv   = (float*)p;
    cudaGetSymbolAddress(&p, g_deg);    int*   deg    = (int*)p;
    cudaGetSymbolAddress(&p, g_rowptr); int*   rowptr = (int*)p;
    cudaGetSymbolAddress(&p, g_fill);   int*   fill   = (int*)p;
    cudaGetSymbolAddress(&p, g_csrc);   int*   csrc   = (int*)p;
    cudaGetSymbolAddress(&p, g_bsum);   int*   bsum   = (int*)p;
    cudaGetSymbolAddress(&p, g_boff);   int*   boff   = (int*)p;
    cudaGetSymbolAddress(&p, g_w1t);    __half* w1t   = (__half*)p;
    cudaGetSymbolAddress(&p, g_w2t);    __half* w2t   = (__half*)p;

    static cudaStream_t s1 = nullptr;
    static cudaEvent_t  ePrep = nullptr, eGemm1 = nullptr;
    if (!s1) {
        cudaStreamCreateWithFlags(&s1, cudaStreamNonBlocking);
        cudaEventCreateWithFlags(&ePrep,  cudaEventDisableTiming);
        cudaEventCreateWithFlags(&eGemm1, cudaEventDisableTiming);
    }

    const int warpsGrid = (NN * 32 + 255) / 256;
    const int gemmGrid  = (NN + 127) / 128;

    // ---- main: prep (deg=0 + weight transposes) ----
    prep_kernel<<<(NN + 255) / 256, 256>>>(deg, W1, W2, w1t, w2t);
    cudaEventRecord(ePrep, 0);

    // ---- s1: GEMM1 (fp32 in, raw fp16 out) starts right after prep ----
    cudaStreamWaitEvent(s1, ePrep, 0);
    mma_gemm_kernel<HID, 2, 4, false, false, false, true><<<gemmGrid, 256, 0, s1>>>(
        x, w1t, nullptr, nullptr, h1, NN, IND);
    cudaEventRecord(eGemm1, s1);

    // ---- main: CSR chain overlaps GEMM1 ----
    deg_count_kernel<<<(E + 255) / 256, 256>>>(dst, deg, E);
    scan_reduce_kernel<<<SC_NB, SC_T>>>(deg, bsum, dinv, NN);
    scan_offsets_kernel<<<1, 128>>>(bsum, boff, rowptr, NN);
    scan_write_kernel<<<SC_NB, SC_T>>>(deg, boff, rowptr, fill, NN);
    fill_kernel<<<(E + 255) / 256, 256>>>(src, dst, fill, csrc, E);

    // ---- join, serial tail ----
    cudaStreamWaitEvent(0, eGemm1, 0);
    gather128_kernel<<<warpsGrid, 256>>>((const uint2*)h1, csrc, rowptr, dinv, (uint2*)agg1);
    mma_gemm_kernel<OUTD, 4, 2, true, true, true, true><<<gemmGrid, 256>>>(
        agg1, w2t, b1, dinv, h2, NN, HID);
    gather64_kernel<<<warpsGrid, 256>>>((const uint32_t*)h2, csrc, rowptr, dinv, b2, (float2*)out);
}